// round 14
// baseline (speedup 1.0000x reference)
#include <cuda_runtime.h>
#include <math.h>
#include <stdint.h>

#define EPS       1e-6f
#define KC        64
#define NB        80               // padded B rows: 64 comms + ones col (64) + zero pad
#define O_DIM     1024
#define M_TILE    128
#define OSTG      64               // O elems per stage
#define NSTG      (O_DIM / OSTG)   // 16
#define AS_STRIDE 80               // bytes per A smem row (bank-spread: 20 words)
#define A_STAGE   (M_TILE * AS_STRIDE)          // 10240
#define BS_STRIDE 1040             // bytes per B smem row (260 words -> 4-bank stride)
#define OFF_A     0
#define OFF_B     (2 * A_STAGE)                 // 20480
#define OFF_MISC  (OFF_B + NB * BS_STRIDE)      // 103680
#define LS_STRIDE 73               // s32 logits row stride (odd -> conflict-free)
#define SMEM_BYTES (OFF_MISC + 1792)

// Scratch: quantized log-weights, per-community scale/offset, tile partials.
__device__ int8_t g_qw[NB * O_DIM];
__device__ float  g_scl[KC], g_off[KC];
__device__ float  g_partials[1024];

// Per-community affine quantization of log(otu+EPS): w = a_k * q + b_k.
__global__ void prep_quant(const float* __restrict__ otu) {
    __shared__ float w[O_DIM];
    __shared__ float red[18];
    const int k   = blockIdx.x;
    const int tid = threadIdx.x;   // 256
    if (k >= KC) {                 // ones column (row sums) + zero padding
        const int8_t val = (k == KC) ? (int8_t)1 : (int8_t)0;
        for (int o = tid; o < O_DIM; o += 256) g_qw[k * O_DIM + o] = val;
        return;
    }
    float lmin = 1e30f, lmax = -1e30f;
    for (int o = tid; o < O_DIM; o += 256) {
        float v = logf(otu[k * O_DIM + o] + EPS);
        w[o] = v;
        lmin = fminf(lmin, v);
        lmax = fmaxf(lmax, v);
    }
#pragma unroll
    for (int d = 16; d; d >>= 1) {
        lmin = fminf(lmin, __shfl_xor_sync(0xffffffffu, lmin, d));
        lmax = fmaxf(lmax, __shfl_xor_sync(0xffffffffu, lmax, d));
    }
    if ((tid & 31) == 0) { red[tid >> 5] = lmin; red[8 + (tid >> 5)] = lmax; }
    __syncthreads();
    if (tid == 0) {
        float mn = red[0], mx = red[8];
#pragma unroll
        for (int i = 1; i < 8; ++i) { mn = fminf(mn, red[i]); mx = fmaxf(mx, red[8 + i]); }
        float a = (mx - mn) / 254.f;
        if (a < 1e-20f) a = 1.f;
        red[16] = a;
        red[17] = 0.5f * (mx + mn);
        g_scl[k] = a;
        g_off[k] = red[17];
    }
    __syncthreads();
    const float inv = 1.f / red[16], b = red[17];
    for (int o = tid; o < O_DIM; o += 256) {
        int q = __float2int_rn((w[o] - b) * inv);
        q = max(-127, min(127, q));
        g_qw[k * O_DIM + o] = (int8_t)q;
    }
}

__device__ __forceinline__ uint32_t s2u(const void* p) {
    uint32_t a;
    asm("{ .reg .u64 t; cvta.to.shared.u64 t, %1; cvt.u32.u64 %0, t; }" : "=r"(a) : "l"(p));
    return a;
}
__device__ __forceinline__ void cp16(uint32_t dst, const void* src) {
    asm volatile("cp.async.cg.shared.global [%0], [%1], 16;\n" :: "r"(dst), "l"(src));
}
__device__ __forceinline__ void imma(int c[4], const uint32_t a[4], const uint32_t b[2]) {
    asm volatile(
        "mma.sync.aligned.m16n8k32.row.col.s32.s8.s8.s32 "
        "{%0,%1,%2,%3}, {%4,%5,%6,%7}, {%8,%9}, {%0,%1,%2,%3};\n"
        : "+r"(c[0]), "+r"(c[1]), "+r"(c[2]), "+r"(c[3])
        : "r"(a[0]), "r"(a[1]), "r"(a[2]), "r"(a[3]), "r"(b[0]), "r"(b[1]));
}
__device__ __forceinline__ uint32_t ld32s(const uint8_t* p) {
    return *reinterpret_cast<const uint32_t*>(p);
}

// fp32 (exact small ints) -> packed s8x4, via FADD 2^23 magic + PRMT. No F2I.
__device__ __forceinline__ void cvt32(const float4 v[8], uint32_t out[8]) {
#pragma unroll
    for (int j = 0; j < 8; ++j) {
        uint32_t u0 = __float_as_uint(v[j].x + 8388608.f);
        uint32_t u1 = __float_as_uint(v[j].y + 8388608.f);
        uint32_t u2 = __float_as_uint(v[j].z + 8388608.f);
        uint32_t u3 = __float_as_uint(v[j].w + 8388608.f);
        uint32_t t0 = __byte_perm(u0, u1, 0x0040);
        uint32_t t1 = __byte_perm(u2, u3, 0x0040);
        out[j] = __byte_perm(t0, t1, 0x5410);
    }
}

// One CTA = 128 rows. 8 warps: warpM 0..3 (32 rows), warpN 0..1 (n-tiles 0-4 / 5-9).
// B (80x1024 s8) resident in smem for the whole CTA; A double-buffered with
// batched LDG.128 prefetch + register convert. Integer GEMM is exact.
__global__ __launch_bounds__(256, 2) void gemm_lse(const float* __restrict__ counts,
                                                   const float* __restrict__ comm,
                                                   int nRows) {
    extern __shared__ __align__(16) uint8_t dynb[];
    const uint32_t base = s2u(dynb);

    float* s_scl   = reinterpret_cast<float*>(dynb + OFF_MISC);
    float* s_off   = s_scl + 64;
    float* s_prior = s_off + 64;
    float* s_red   = s_prior + 64;

    const int tid   = threadIdx.x;
    const int lane  = tid & 31;
    const int warp  = tid >> 5;
    const int warpM = warp >> 1;
    const int warpN = warp & 1;
    const int g     = lane >> 2;
    const int t     = lane & 3;

    if (tid < KC) {
        s_scl[tid]   = g_scl[tid];
        s_off[tid]   = g_off[tid];
        s_prior[tid] = logf(comm[tid] + EPS);
    }

    // ---- load whole B into smem (once; from L2-resident g_qw) ----
    for (int c = tid; c < NB * O_DIM / 16; c += 256) {
        const int row = c >> 6;
        const int ko  = (c & 63) * 16;
        cp16(base + OFF_B + row * BS_STRIDE + ko, g_qw + row * O_DIM + ko);
    }
    asm volatile("cp.async.commit_group;\n");

    const int rowBase = blockIdx.x * M_TILE;

    int acc[2][5][4];
#pragma unroll
    for (int mt = 0; mt < 2; ++mt)
#pragma unroll
        for (int nt = 0; nt < 5; ++nt)
#pragma unroll
            for (int i = 0; i < 4; ++i) acc[mt][nt][i] = 0;

    // A staging role: thread -> row tid/2, half tid&1 (32 floats -> 32 s8).
    const int r    = tid >> 1;
    const int h    = tid & 1;
    const int gr   = rowBase + r;
    const int grc  = (gr < nRows) ? gr : (nRows - 1);  // clamp addr; masked later
    const float4* aSrc = reinterpret_cast<const float4*>(counts + (size_t)grc * O_DIM + h * 32);

    float4 v[8];
#pragma unroll
    for (int i = 0; i < 8; ++i) v[i] = aSrc[i];        // stage 0, batched

    for (int s = 0; s < NSTG; ++s) {
        // convert staged floats (stage s) and commit to smem buffer s&1
        uint32_t out[8];
        cvt32(v, out);
        {
            uint32_t* d = reinterpret_cast<uint32_t*>(dynb + OFF_A + (s & 1) * A_STAGE +
                                                      r * AS_STRIDE + h * 32);
            d[0] = out[0]; d[1] = out[1]; d[2] = out[2]; d[3] = out[3];
            d[4] = out[4]; d[5] = out[5]; d[6] = out[6]; d[7] = out[7];
        }
        if (s == 0) asm volatile("cp.async.wait_group 0;\n");  // B resident
        __syncthreads();

        // batched prefetch of stage s+1 (latency covered by MMAs below)
        if (s + 1 < NSTG) {
            const float4* src = aSrc + (s + 1) * (OSTG / 4);
#pragma unroll
            for (int i = 0; i < 8; ++i) v[i] = src[i];
        }

        const uint8_t* As = dynb + OFF_A + (s & 1) * A_STAGE;
        const uint8_t* Bs = dynb + OFF_B;
#pragma unroll
        for (int kc = 0; kc < 2; ++kc) {
            uint32_t a[2][4];
#pragma unroll
            for (int mt = 0; mt < 2; ++mt) {
                const uint8_t* p = As + (warpM * 32 + mt * 16 + g) * AS_STRIDE + kc * 32 + 4 * t;
                a[mt][0] = ld32s(p);
                a[mt][1] = ld32s(p + 8 * AS_STRIDE);
                a[mt][2] = ld32s(p + 16);
                a[mt][3] = ld32s(p + 8 * AS_STRIDE + 16);
            }
            uint32_t b[5][2];
#pragma unroll
            for (int nt = 0; nt < 5; ++nt) {
                const uint8_t* p = Bs + (warpN * 40 + nt * 8 + g) * BS_STRIDE +
                                   s * OSTG + kc * 32 + 4 * t;
                b[nt][0] = ld32s(p);
                b[nt][1] = ld32s(p + 16);
            }
#pragma unroll
            for (int mt = 0; mt < 2; ++mt)
#pragma unroll
                for (int nt = 0; nt < 5; ++nt)
                    imma(acc[mt][nt], a[mt], b[nt]);
        }
    }
    __syncthreads();   // all B reads done before logits overwrite B region

    // ---- spill s32 logits (cols 0..71; tile 9 = zero pad, skipped) ----
    int* Li = reinterpret_cast<int*>(dynb + OFF_B);
#pragma unroll
    for (int mt = 0; mt < 2; ++mt) {
        const int r0 = warpM * 32 + mt * 16 + g;
#pragma unroll
        for (int nt = 0; nt < 5; ++nt) {
            if (warpN == 1 && nt == 4) continue;
            const int c0 = warpN * 40 + nt * 8 + 2 * t;
            Li[r0 * LS_STRIDE + c0]           = acc[mt][nt][0];
            Li[r0 * LS_STRIDE + c0 + 1]       = acc[mt][nt][1];
            Li[(r0 + 8) * LS_STRIDE + c0]     = acc[mt][nt][2];
            Li[(r0 + 8) * LS_STRIDE + c0 + 1] = acc[mt][nt][3];
        }
    }
    __syncthreads();

    // ---- per-row logsumexp: 2 threads/row; logits = a_k*idot + b_k*S + prior_k ----
    float val = 0.f;
    {
        const int row = tid >> 1;
        const int kh  = (tid & 1) * 32;
        const float S = (float)Li[row * LS_STRIDE + 64];   // ones-column = row count sum
        float x[32];
        float m = -INFINITY;
#pragma unroll
        for (int k = 0; k < 32; ++k) {
            const int kk = kh + k;
            x[k] = s_scl[kk] * (float)Li[row * LS_STRIDE + kk] + s_off[kk] * S + s_prior[kk];
            m = fmaxf(m, x[k]);
        }
        const float mo = __shfl_xor_sync(0xffffffffu, m, 1);
        const float mm = fmaxf(m, mo);
        float ssum = 0.f;
#pragma unroll
        for (int k = 0; k < 32; ++k)
            ssum += __expf(x[k] - mm);
        const float so = __shfl_xor_sync(0xffffffffu, ssum, 1);
        if ((tid & 1) == 0 && (rowBase + row) < nRows)
            val = mm + __logf(ssum + so);
    }
    s_red[tid] = val;
    __syncthreads();
#pragma unroll
    for (int off = 128; off > 0; off >>= 1) {
        if (tid < off) s_red[tid] += s_red[tid + off];
        __syncthreads();
    }
    if (tid == 0) g_partials[blockIdx.x] = s_red[0];
}

__global__ void final_reduce(float* __restrict__ out, int nTiles) {
    __shared__ double sred[256];
    double s = 0.0;
    for (int i = threadIdx.x; i < nTiles; i += 256) s += (double)g_partials[i];
    sred[threadIdx.x] = s;
    __syncthreads();
#pragma unroll
    for (int off = 128; off > 0; off >>= 1) {
        if (threadIdx.x < off) sred[threadIdx.x] += sred[threadIdx.x + off];
        __syncthreads();
    }
    if (threadIdx.x == 0) out[0] = (float)sred[0];
}

extern "C" void kernel_launch(void* const* d_in, const int* in_sizes, int n_in,
                              void* d_out, int out_size) {
    const float* counts = (const float*)d_in[0];   // (N, 1024) fp32
    const float* otu    = (const float*)d_in[1];   // (64, 1024) fp32
    const float* comm   = (const float*)d_in[2];   // (64,) fp32
    float* out = (float*)d_out;

    const int nRows  = in_sizes[0] / O_DIM;
    const int nTiles = (nRows + M_TILE - 1) / M_TILE;

    static bool smem_set = false;  // idempotent attribute, safe under capture
    if (!smem_set) {
        cudaFuncSetAttribute(gemm_lse, cudaFuncAttributeMaxDynamicSharedMemorySize,
                             SMEM_BYTES);
        smem_set = true;
    }

    prep_quant<<<NB, 256>>>(otu);
    gemm_lse<<<nTiles, 256, SMEM_BYTES>>>(counts, comm, nRows);
    final_reduce<<<1, 256>>>(out, nTiles);
}

// round 15
// speedup vs baseline: 1.4603x; 1.4603x over previous
#include <cuda_runtime.h>
#include <math.h>
#include <stdint.h>

#define EPS        1e-6f
#define K_COMM     64
#define O_DIM      1024
#define M_TILE     128
#define OSTG       32                   // O elems per stage
#define NSTG       (O_DIM / OSTG)       // 32
#define PIPE       2
#define AS_F       36                   // fp32 per A smem row (144B, frag-conflict-free)
#define A_STAGE_B  (M_TILE * AS_F * 4)  // 18432 B
#define B_STAGE_B  (OSTG * K_COMM * 4)  // 8192 B (packed frag order, linear)
#define OFF_A      0
#define OFF_B      (PIPE * A_STAGE_B)              // 36864
#define OFF_MISC   (OFF_B + PIPE * B_STAGE_B)      // 53248
#define SMEM_BYTES (OFF_MISC + 1536)
#define LS_STRIDE  65

// Scratch: tf32-rounded log-weights in FRAG-PACKED order + per-tile partials.
// Packed index for B[k][o]: c=o>>3, t=o&3, slot=(o&7)>>2 ->
//   g_logw[c*512 + k*8 + t*2 + slot]
__device__ float g_logw[K_COMM * O_DIM];
__device__ float g_partials[1024];

__global__ void prep_logw(const float* __restrict__ otu) {
    int i = blockIdx.x * blockDim.x + threadIdx.x;
    if (i < K_COMM * O_DIM) {
        const int k = i >> 10;
        const int o = i & 1023;
        float v = logf(otu[i] + EPS);
        uint32_t u;
        asm("cvt.rna.tf32.f32 %0, %1;" : "=r"(u) : "f"(v));
        const int c = o >> 3, t = o & 3, slot = (o & 7) >> 2;
        g_logw[c * 512 + k * 8 + t * 2 + slot] = __uint_as_float(u);
    }
}

__device__ __forceinline__ uint32_t s2u(const void* p) {
    uint32_t a;
    asm("{ .reg .u64 t; cvta.to.shared.u64 t, %1; cvt.u32.u64 %0, t; }" : "=r"(a) : "l"(p));
    return a;
}
__device__ __forceinline__ void cp16(uint32_t dst, const void* src, int bytes) {
    asm volatile("cp.async.cg.shared.global [%0], [%1], 16, %2;\n"
                 :: "r"(dst), "l"(src), "r"(bytes));
}
__device__ __forceinline__ void mma_tf32(float c[4], const uint32_t a[4], const uint32_t b[2]) {
    asm volatile(
        "mma.sync.aligned.m16n8k8.row.col.f32.tf32.tf32.f32 "
        "{%0,%1,%2,%3}, {%4,%5,%6,%7}, {%8,%9}, {%0,%1,%2,%3};\n"
        : "+f"(c[0]), "+f"(c[1]), "+f"(c[2]), "+f"(c[3])
        : "r"(a[0]), "r"(a[1]), "r"(a[2]), "r"(a[3]),
          "r"(b[0]), "r"(b[1]));
}

// One CTA = 128 rows, 8 warps (warpM 0..3 x warpN 0..1), 3 CTAs/SM (24 warps).
// 2-deep cp.async pipeline; B staged from frag-packed g_logw (LDS.64 frags).
__global__ __launch_bounds__(256, 3) void gemm_lse(const float* __restrict__ counts,
                                                   const float* __restrict__ comm,
                                                   int nRows) {
    extern __shared__ __align__(16) uint8_t dynb[];
    const uint32_t base = s2u(dynb);

    float* s_prior = reinterpret_cast<float*>(dynb + OFF_MISC);
    float* s_red   = s_prior + 64;
    float* Ls      = reinterpret_cast<float*>(dynb);   // epilogue reuse (33280 <= 36864)

    const int tid   = threadIdx.x;
    const int lane  = tid & 31;
    const int warp  = tid >> 5;
    const int warpM = warp >> 1;
    const int warpN = warp & 1;
    const int g     = lane >> 2;
    const int t     = lane & 3;

    if (tid < K_COMM) s_prior[tid] = logf(comm[tid] + EPS);

    const int rowBase = blockIdx.x * M_TILE;

    float acc[2][4][4];
#pragma unroll
    for (int mt = 0; mt < 2; ++mt)
#pragma unroll
        for (int nt = 0; nt < 4; ++nt)
#pragma unroll
            for (int i = 0; i < 4; ++i) acc[mt][nt][i] = 0.f;

    // A staging: thread -> row tid/2, half tid&1 (16 floats = 4x 16B).
    const int r    = tid >> 1;
    const int h    = tid & 1;
    const int gr   = rowBase + r;
    const int aSz  = (gr < nRows) ? 16 : 0;
    const int grc  = (gr < nRows) ? gr : (nRows - 1);
    const float* aSrc = counts + (size_t)grc * O_DIM + h * 16;
    const uint32_t dA0 = base + OFF_A + (uint32_t)((r * AS_F + h * 16) * 4);
    // B staging: linear 8 KB; thread -> 2x 16B at tid*32.
    const float* bSrc = g_logw + tid * 8;
    const uint32_t dB0 = base + OFF_B + (uint32_t)(tid * 32);

    auto issue = [&](int s) {
        const uint32_t dA = dA0 + (uint32_t)((s & 1) * A_STAGE_B);
        const float* sA = aSrc + s * OSTG;
#pragma unroll
        for (int i = 0; i < 4; ++i)
            cp16(dA + i * 16, sA + i * 4, aSz);
        const uint32_t dB = dB0 + (uint32_t)((s & 1) * B_STAGE_B);
        const float* sB = bSrc + s * (OSTG * K_COMM);
        cp16(dB,      sB,     16);
        cp16(dB + 16, sB + 4, 16);
        asm volatile("cp.async.commit_group;\n");
    };

    issue(0);   // prologue

    for (int s = 0; s < NSTG; ++s) {
        asm volatile("cp.async.wait_group 0;\n");   // stage s landed (this thread)
        __syncthreads();                            // visible to all; prior MMAs done

        if (s + 1 < NSTG) issue(s + 1);             // overlaps MMA below

        const float* As = reinterpret_cast<const float*>(dynb + OFF_A + (s & 1) * A_STAGE_B);
        const float* Bs = reinterpret_cast<const float*>(dynb + OFF_B + (s & 1) * B_STAGE_B);

#pragma unroll
        for (int cl = 0; cl < OSTG / 8; ++cl) {     // 4 k-chunks of 8
            uint32_t a[2][4];
#pragma unroll
            for (int mt = 0; mt < 2; ++mt) {
                const float* p = As + (warpM * 32 + mt * 16 + g) * AS_F + cl * 8 + t;
                a[mt][0] = __float_as_uint(p[0]);
                a[mt][1] = __float_as_uint(p[8 * AS_F]);
                a[mt][2] = __float_as_uint(p[4]);
                a[mt][3] = __float_as_uint(p[8 * AS_F + 4]);
            }
            uint32_t b[4][2];
#pragma unroll
            for (int nt = 0; nt < 4; ++nt) {
                const float2 bv = *reinterpret_cast<const float2*>(
                    Bs + cl * 512 + (warpN * 32 + nt * 8 + g) * 8 + 2 * t);
                b[nt][0] = __float_as_uint(bv.x);
                b[nt][1] = __float_as_uint(bv.y);
            }
#pragma unroll
            for (int mt = 0; mt < 2; ++mt)
#pragma unroll
                for (int nt = 0; nt < 4; ++nt)
                    mma_tf32(acc[mt][nt], a[mt], b[nt]);
        }
    }
    __syncthreads();   // all MMA reads done before Ls aliases the buffers

    // ---- spill logits (C-frag -> row-major [128][64], stride 65) ----
#pragma unroll
    for (int mt = 0; mt < 2; ++mt) {
        const int r0 = warpM * 32 + mt * 16 + g;
#pragma unroll
        for (int nt = 0; nt < 4; ++nt) {
            const int c0 = warpN * 32 + nt * 8 + 2 * t;
            Ls[r0 * LS_STRIDE + c0]           = acc[mt][nt][0];
            Ls[r0 * LS_STRIDE + c0 + 1]       = acc[mt][nt][1];
            Ls[(r0 + 8) * LS_STRIDE + c0]     = acc[mt][nt][2];
            Ls[(r0 + 8) * LS_STRIDE + c0 + 1] = acc[mt][nt][3];
        }
    }
    __syncthreads();

    // ---- per-row logsumexp: 2 threads per row, shfl-combined ----
    float val = 0.f;
    {
        const int row = tid >> 1;
        const int kh  = (tid & 1) * 32;
        float m = -INFINITY;
        float x[32];
#pragma unroll
        for (int k = 0; k < 32; ++k) {
            x[k] = Ls[row * LS_STRIDE + kh + k] + s_prior[kh + k];
            m = fmaxf(m, x[k]);
        }
        const float mo = __shfl_xor_sync(0xffffffffu, m, 1);
        const float mm = fmaxf(m, mo);
        float ssum = 0.f;
#pragma unroll
        for (int k = 0; k < 32; ++k)
            ssum += __expf(x[k] - mm);
        const float so = __shfl_xor_sync(0xffffffffu, ssum, 1);
        if ((tid & 1) == 0 && (rowBase + row) < nRows)
            val = mm + __logf(ssum + so);
    }
    s_red[tid] = val;
    __syncthreads();
#pragma unroll
    for (int off = 128; off > 0; off >>= 1) {
        if (tid < off) s_red[tid] += s_red[tid + off];
        __syncthreads();
    }
    if (tid == 0) g_partials[blockIdx.x] = s_red[0];
}

__global__ void final_reduce(float* __restrict__ out, int nTiles) {
    __shared__ double sred[256];
    double s = 0.0;
    for (int i = threadIdx.x; i < nTiles; i += 256) s += (double)g_partials[i];
    sred[threadIdx.x] = s;
    __syncthreads();
#pragma unroll
    for (int off = 128; off > 0; off >>= 1) {
        if (threadIdx.x < off) sred[threadIdx.x] += sred[threadIdx.x + off];
        __syncthreads();
    }
    if (threadIdx.x == 0) out[0] = (float)sred[0];
}

extern "C" void kernel_launch(void* const* d_in, const int* in_sizes, int n_in,
                              void* d_out, int out_size) {
    const float* counts = (const float*)d_in[0];   // (N, 1024) fp32
    const float* otu    = (const float*)d_in[1];   // (64, 1024) fp32
    const float* comm   = (const float*)d_in[2];   // (64,) fp32
    float* out = (float*)d_out;

    const int nRows  = in_sizes[0] / O_DIM;
    const int nTiles = (nRows + M_TILE - 1) / M_TILE;

    static bool smem_set = false;  // idempotent attribute, safe under capture
    if (!smem_set) {
        cudaFuncSetAttribute(gemm_lse, cudaFuncAttributeMaxDynamicSharedMemorySize,
                             SMEM_BYTES);
        smem_set = true;
    }

    prep_logw<<<(K_COMM * O_DIM + 255) / 256, 256>>>(otu);
    gemm_lse<<<nTiles, 256, SMEM_BYTES>>>(counts, comm, nRows);
    final_reduce<<<1, 256>>>(out, nTiles);
}

// round 16
// speedup vs baseline: 1.6722x; 1.1451x over previous
#include <cuda_runtime.h>
#include <math.h>
#include <stdint.h>

#define EPS        1e-6f
#define K_COMM     64
#define O_DIM      1024
#define M_TILE     128
#define OSTG       16                   // O elems per stage
#define NSTG       (O_DIM / OSTG)       // 64
#define PIPE       4
#define AS_F       20                   // fp32 per A smem row (80B: all-32-banks frag pattern)
#define A_STAGE_B  (M_TILE * AS_F * 4)  // 10240 B
#define B_STAGE_B  (OSTG * K_COMM * 4)  // 4096 B (frag-packed, linear)
#define OFF_A      0
#define OFF_B      (PIPE * A_STAGE_B)              // 40960
#define OFF_MISC   (OFF_B + PIPE * B_STAGE_B)      // 57344
#define SMEM_BYTES (OFF_MISC + 1536)               // 58880 -> 3 CTAs/SM
#define LS_STRIDE  65

// Scratch: tf32-rounded log-weights in FRAG-PACKED order + per-tile partials.
// Packed index for B[k][o]: c=o>>3, t=o&3, slot=(o&7)>>2 ->
//   g_logw[c*512 + k*8 + t*2 + slot]   (stage s = chunks 2s..2s+1 = contiguous 1024 floats)
__device__ float g_logw[K_COMM * O_DIM];
__device__ float g_partials[1024];

__global__ void prep_logw(const float* __restrict__ otu) {
    int i = blockIdx.x * blockDim.x + threadIdx.x;
    if (i < K_COMM * O_DIM) {
        const int k = i >> 10;
        const int o = i & 1023;
        float v = logf(otu[i] + EPS);
        uint32_t u;
        asm("cvt.rna.tf32.f32 %0, %1;" : "=r"(u) : "f"(v));
        const int c = o >> 3, t = o & 3, slot = (o & 7) >> 2;
        g_logw[c * 512 + k * 8 + t * 2 + slot] = __uint_as_float(u);
    }
}

__device__ __forceinline__ uint32_t s2u(const void* p) {
    uint32_t a;
    asm("{ .reg .u64 t; cvta.to.shared.u64 t, %1; cvt.u32.u64 %0, t; }" : "=r"(a) : "l"(p));
    return a;
}
__device__ __forceinline__ void cp16(uint32_t dst, const void* src, int bytes) {
    asm volatile("cp.async.cg.shared.global [%0], [%1], 16, %2;\n"
                 :: "r"(dst), "l"(src), "r"(bytes));
}
__device__ __forceinline__ void mma_tf32(float c[4], const uint32_t a[4], const uint32_t b[2]) {
    asm volatile(
        "mma.sync.aligned.m16n8k8.row.col.f32.tf32.tf32.f32 "
        "{%0,%1,%2,%3}, {%4,%5,%6,%7}, {%8,%9}, {%0,%1,%2,%3};\n"
        : "+f"(c[0]), "+f"(c[1]), "+f"(c[2]), "+f"(c[3])
        : "r"(a[0]), "r"(a[1]), "r"(a[2]), "r"(a[3]),
          "r"(b[0]), "r"(b[1]));
}

// One CTA = 128 rows, 8 warps (warpM 0..3 x warpN 0..1), 3 CTAs/SM.
// 4-deep cp.async pipeline, wait_group 2 => 2 compute-stages of latency slack.
__global__ __launch_bounds__(256, 3) void gemm_lse(const float* __restrict__ counts,
                                                   const float* __restrict__ comm,
                                                   int nRows) {
    extern __shared__ __align__(16) uint8_t dynb[];
    const uint32_t base = s2u(dynb);

    float* s_prior = reinterpret_cast<float*>(dynb + OFF_MISC);
    float* s_red   = s_prior + 64;
    float* Ls      = reinterpret_cast<float*>(dynb);   // epilogue reuse (33280 <= 40960)

    const int tid   = threadIdx.x;
    const int lane  = tid & 31;
    const int warp  = tid >> 5;
    const int warpM = warp >> 1;
    const int warpN = warp & 1;
    const int g     = lane >> 2;
    const int t     = lane & 3;

    if (tid < K_COMM) s_prior[tid] = logf(comm[tid] + EPS);

    const int rowBase = blockIdx.x * M_TILE;

    float acc[2][4][4];
#pragma unroll
    for (int mt = 0; mt < 2; ++mt)
#pragma unroll
        for (int nt = 0; nt < 4; ++nt)
#pragma unroll
            for (int i = 0; i < 4; ++i) acc[mt][nt][i] = 0.f;

    // A staging: thread -> row tid/2, half tid&1 (8 floats = 2x 16B).
    const int r    = tid >> 1;
    const int h    = tid & 1;
    const int gr   = rowBase + r;
    const int aSz  = (gr < nRows) ? 16 : 0;
    const int grc  = (gr < nRows) ? gr : (nRows - 1);
    const float* aSrc = counts + (size_t)grc * O_DIM + h * 8;
    const uint32_t dA0 = base + OFF_A + (uint32_t)((r * AS_F + h * 8) * 4);
    // B staging: linear 4 KB/stage; thread -> 1x 16B at tid*16.
    const float* bSrc = g_logw + tid * 4;
    const uint32_t dB0 = base + OFF_B + (uint32_t)(tid * 16);

    auto issue = [&](int s) {
        const uint32_t dA = dA0 + (uint32_t)((s & (PIPE - 1)) * A_STAGE_B);
        const float* sA = aSrc + s * OSTG;
        cp16(dA,      sA,     aSz);
        cp16(dA + 16, sA + 4, aSz);
        const uint32_t dB = dB0 + (uint32_t)((s & (PIPE - 1)) * B_STAGE_B);
        cp16(dB, bSrc + s * (OSTG * K_COMM), 16);
        asm volatile("cp.async.commit_group;\n");
    };

    // Prologue: fill PIPE-1 stages.
#pragma unroll
    for (int ps = 0; ps < PIPE - 1; ++ps) issue(ps);

    for (int s = 0; s < NSTG; ++s) {
        asm volatile("cp.async.wait_group %0;\n" :: "n"(PIPE - 2));  // stage s landed
        __syncthreads();          // visible to all; all warps past stage s-1 MMAs

        if (s + PIPE - 1 < NSTG) issue(s + PIPE - 1);   // refill buffer (s-1)&3

        const float* As = reinterpret_cast<const float*>(
            dynb + OFF_A + (s & (PIPE - 1)) * A_STAGE_B);
        const float* Bs = reinterpret_cast<const float*>(
            dynb + OFF_B + (s & (PIPE - 1)) * B_STAGE_B);

#pragma unroll
        for (int cl = 0; cl < OSTG / 8; ++cl) {     // 2 k-chunks of 8
            uint32_t a[2][4];
#pragma unroll
            for (int mt = 0; mt < 2; ++mt) {
                const float* p = As + (warpM * 32 + mt * 16 + g) * AS_F + cl * 8 + t;
                a[mt][0] = __float_as_uint(p[0]);
                a[mt][1] = __float_as_uint(p[8 * AS_F]);
                a[mt][2] = __float_as_uint(p[4]);
                a[mt][3] = __float_as_uint(p[8 * AS_F + 4]);
            }
            uint32_t b[4][2];
#pragma unroll
            for (int nt = 0; nt < 4; ++nt) {
                const float2 bv = *reinterpret_cast<const float2*>(
                    Bs + cl * 512 + (warpN * 32 + nt * 8 + g) * 8 + 2 * t);
                b[nt][0] = __float_as_uint(bv.x);
                b[nt][1] = __float_as_uint(bv.y);
            }
#pragma unroll
            for (int mt = 0; mt < 2; ++mt)
#pragma unroll
                for (int nt = 0; nt < 4; ++nt)
                    mma_tf32(acc[mt][nt], a[mt], b[nt]);
        }
    }
    __syncthreads();   // all MMA reads done before Ls aliases the buffers

    // ---- spill logits (C-frag -> row-major [128][64], stride 65) ----
#pragma unroll
    for (int mt = 0; mt < 2; ++mt) {
        const int r0 = warpM * 32 + mt * 16 + g;
#pragma unroll
        for (int nt = 0; nt < 4; ++nt) {
            const int c0 = warpN * 32 + nt * 8 + 2 * t;
            Ls[r0 * LS_STRIDE + c0]           = acc[mt][nt][0];
            Ls[r0 * LS_STRIDE + c0 + 1]       = acc[mt][nt][1];
            Ls[(r0 + 8) * LS_STRIDE + c0]     = acc[mt][nt][2];
            Ls[(r0 + 8) * LS_STRIDE + c0 + 1] = acc[mt][nt][3];
        }
    }
    __syncthreads();

    // ---- per-row logsumexp: 2 threads per row, shfl-combined ----
    float val = 0.f;
    {
        const int row = tid >> 1;
        const int kh  = (tid & 1) * 32;
        float m = -INFINITY;
        float x[32];
#pragma unroll
        for (int k = 0; k < 32; ++k) {
            x[k] = Ls[row * LS_STRIDE + kh + k] + s_prior[kh + k];
            m = fmaxf(m, x[k]);
        }
        const float mo = __shfl_xor_sync(0xffffffffu, m, 1);
        const float mm = fmaxf(m, mo);
        float ssum = 0.f;
#pragma unroll
        for (int k = 0; k < 32; ++k)
            ssum += __expf(x[k] - mm);
        const float so = __shfl_xor_sync(0xffffffffu, ssum, 1);
        if ((tid & 1) == 0 && (rowBase + row) < nRows)
            val = mm + __logf(ssum + so);
    }
    // warp-level sum then cross-warp via smem (2 barriers total)
#pragma unroll
    for (int d = 16; d; d >>= 1) val += __shfl_xor_sync(0xffffffffu, val, d);
    if (lane == 0) s_red[warp] = val;
    __syncthreads();
    if (warp == 0) {
        float v = (lane < 8) ? s_red[lane] : 0.f;
#pragma unroll
        for (int d = 4; d; d >>= 1) v += __shfl_xor_sync(0xffffffffu, v, d);
        if (lane == 0) g_partials[blockIdx.x] = v;
    }
}

__global__ void final_reduce(float* __restrict__ out, int nTiles) {
    __shared__ double sred[256];
    double s = 0.0;
    for (int i = threadIdx.x; i < nTiles; i += 256) s += (double)g_partials[i];
    sred[threadIdx.x] = s;
    __syncthreads();
#pragma unroll
    for (int off = 128; off > 0; off >>= 1) {
        if (threadIdx.x < off) sred[threadIdx.x] += sred[threadIdx.x + off];
        __syncthreads();
    }
    if (threadIdx.x == 0) out[0] = (float)sred[0];
}

extern "C" void kernel_launch(void* const* d_in, const int* in_sizes, int n_in,
                              void* d_out, int out_size) {
    const float* counts = (const float*)d_in[0];   // (N, 1024) fp32
    const float* otu    = (const float*)d_in[1];   // (64, 1024) fp32
    const float* comm   = (const float*)d_in[2];   // (64,) fp32
    float* out = (float*)d_out;

    const int nRows  = in_sizes[0] / O_DIM;
    const int nTiles = (nRows + M_TILE - 1) / M_TILE;

    static bool smem_set = false;  // idempotent attribute, safe under capture
    if (!smem_set) {
        cudaFuncSetAttribute(gemm_lse, cudaFuncAttributeMaxDynamicSharedMemorySize,
                             SMEM_BYTES);
        smem_set = true;
    }

    prep_logw<<<(K_COMM * O_DIM + 255) / 256, 256>>>(otu);
    gemm_lse<<<nTiles, 256, SMEM_BYTES>>>(counts, comm, nRows);
    final_reduce<<<1, 256>>>(out, nTiles);
}

// round 17
// speedup vs baseline: 1.7823x; 1.0658x over previous
#include <cuda_runtime.h>
#include <cuda_bf16.h>
#include <math.h>
#include <stdint.h>

#define EPS        1e-6f
#define K_COMM     64
#define O_DIM      1024
#define M_TILE     128
#define OSTG       32                    // O elems per stage (2 k16 chunks)
#define NSTG       (O_DIM / OSTG)        // 32
#define PIPE       3
#define AS_W       40                    // fp32 words per A row (160B: conflict-free g*8+2t)
#define A_STAGE_B  (M_TILE * AS_W * 4)   // 20480 B
#define B_STAGE_B  4096                  // 2 chunks x 2048 B (bf16 frag-packed)
#define OFF_A      0
#define OFF_B      (PIPE * A_STAGE_B)               // 61440
#define OFF_MISC   (OFF_B + PIPE * B_STAGE_B)       // 73728
#define SMEM_BYTES (OFF_MISC + 512)                 // 74240 -> 3 CTAs/SM
#define LS_STRIDE  65

// B in bf16x2, m16n8k16-fragment order:
//   for o: chunk c=o>>4, slot=(o>>3)&1, tf=(o>>1)&3
//   g_logwB[((c*64 + n)*4 + tf)*2 + slot] = {log[n][o_even], log[n][o_even+1]}
__device__ uint32_t g_logwB[K_COMM * O_DIM / 2];
__device__ float    g_partials[1024];

__global__ void prep_logw(const float* __restrict__ otu) {
    int i = blockIdx.x * blockDim.x + threadIdx.x;   // 64*512 pairs
    if (i < K_COMM * 512) {
        const int n = i >> 9;
        const int o = (i & 511) * 2;
        float v0 = logf(otu[n * O_DIM + o]     + EPS);
        float v1 = logf(otu[n * O_DIM + o + 1] + EPS);
        __nv_bfloat162 h = __floats2bfloat162_rn(v0, v1);
        const int c = o >> 4, slot = (o >> 3) & 1, tf = (o >> 1) & 3;
        g_logwB[((c * 64 + n) * 4 + tf) * 2 + slot] = *reinterpret_cast<uint32_t*>(&h);
    }
}

__device__ __forceinline__ uint32_t s2u(const void* p) {
    uint32_t a;
    asm("{ .reg .u64 t; cvta.to.shared.u64 t, %1; cvt.u32.u64 %0, t; }" : "=r"(a) : "l"(p));
    return a;
}
__device__ __forceinline__ void cp16(uint32_t dst, const void* src, int bytes) {
    asm volatile("cp.async.cg.shared.global [%0], [%1], 16, %2;\n"
                 :: "r"(dst), "l"(src), "r"(bytes));
}
__device__ __forceinline__ uint32_t pack2(float a, float b) {
    __nv_bfloat162 h = __floats2bfloat162_rn(a, b);
    return *reinterpret_cast<uint32_t*>(&h);
}
__device__ __forceinline__ void mma16816(float c[4], const uint32_t a[4], const uint32_t b[2]) {
    asm volatile(
        "mma.sync.aligned.m16n8k16.row.col.f32.bf16.bf16.f32 "
        "{%0,%1,%2,%3}, {%4,%5,%6,%7}, {%8,%9}, {%0,%1,%2,%3};\n"
        : "+f"(c[0]), "+f"(c[1]), "+f"(c[2]), "+f"(c[3])
        : "r"(a[0]), "r"(a[1]), "r"(a[2]), "r"(a[3]),
          "r"(b[0]), "r"(b[1]));
}

// One CTA = 128 rows, 8 warps (warpM 0..3 x warpN 0..1), 3 CTAs/SM.
// cp.async stages fp32 A + frag-packed bf16 B; A converted at frag load
// (LDS.64 fp32 pair + F2FP pack) -> bf16 k16 MMA (half the tensor instrs of tf32).
__global__ __launch_bounds__(256, 3) void gemm_lse(const float* __restrict__ counts,
                                                   const float* __restrict__ comm,
                                                   int nRows) {
    extern __shared__ __align__(16) uint8_t dynb[];
    const uint32_t base = s2u(dynb);

    float* s_prior = reinterpret_cast<float*>(dynb + OFF_MISC);
    float* s_red   = s_prior + 64;
    float* Ls      = reinterpret_cast<float*>(dynb);   // epilogue reuse (33280 <= 61440)

    const int tid   = threadIdx.x;
    const int lane  = tid & 31;
    const int warp  = tid >> 5;
    const int warpM = warp >> 1;
    const int warpN = warp & 1;
    const int g     = lane >> 2;
    const int t     = lane & 3;

    if (tid < K_COMM) s_prior[tid] = logf(comm[tid] + EPS);

    const int rowBase = blockIdx.x * M_TILE;

    float acc[2][4][4];
#pragma unroll
    for (int mt = 0; mt < 2; ++mt)
#pragma unroll
        for (int nt = 0; nt < 4; ++nt)
#pragma unroll
            for (int i = 0; i < 4; ++i) acc[mt][nt][i] = 0.f;

    // A staging: thread -> row tid/2, half tid&1 (16 floats = 4x 16B per stage).
    const int r    = tid >> 1;
    const int h    = tid & 1;
    const int gr   = rowBase + r;
    const int aSz  = (gr < nRows) ? 16 : 0;           // zfill OOB rows
    const int grc  = (gr < nRows) ? gr : (nRows - 1);
    const float* aSrc = counts + (size_t)grc * O_DIM + h * 16;
    const uint32_t dA0 = base + OFF_A + (uint32_t)(r * 160 + h * 64);
    // B staging: 1x 16B per thread per stage from frag-packed g_logwB.
    const uint32_t dB0 = base + OFF_B + (uint32_t)(tid * 16);
    const uint32_t* bSrc = g_logwB + tid * 4;

    auto issue = [&](int s, int b) {
        const uint32_t dA = dA0 + (uint32_t)(b * A_STAGE_B);
        const float* sA = aSrc + s * OSTG;
#pragma unroll
        for (int i = 0; i < 4; ++i)
            cp16(dA + i * 16, sA + i * 4, aSz);
        cp16(dB0 + (uint32_t)(b * B_STAGE_B), bSrc + s * 1024, 16);
        asm volatile("cp.async.commit_group;\n");
    };

    issue(0, 0);
    issue(1, 1);

    int bufc = 0;   // s % 3
    for (int s = 0; s < NSTG; ++s) {
        asm volatile("cp.async.wait_group 1;\n");   // stage s landed
        __syncthreads();                            // visible; all warps past s-1 MMAs

        {   // refill freed buffer with stage s+2 (always commit to keep group count)
            const int ib = (bufc + 2 >= PIPE) ? bufc + 2 - PIPE : bufc + 2;
            if (s + 2 < NSTG) issue(s + 2, ib);
            else asm volatile("cp.async.commit_group;\n");
        }

        const float*   As = reinterpret_cast<const float*>(dynb + OFF_A + bufc * A_STAGE_B);
        const uint8_t* Bs = dynb + OFF_B + bufc * B_STAGE_B;

#pragma unroll
        for (int cl = 0; cl < 2; ++cl) {            // 2 k16 chunks
            uint32_t a[2][4];
#pragma unroll
            for (int mt = 0; mt < 2; ++mt) {
                const float* p = As + (warpM * 32 + mt * 16 + g) * AS_W + cl * 16 + 2 * t;
                const float2 v0 = *reinterpret_cast<const float2*>(p);
                const float2 v1 = *reinterpret_cast<const float2*>(p + 8 * AS_W);
                const float2 v2 = *reinterpret_cast<const float2*>(p + 8);
                const float2 v3 = *reinterpret_cast<const float2*>(p + 8 * AS_W + 8);
                a[mt][0] = pack2(v0.x, v0.y);
                a[mt][1] = pack2(v1.x, v1.y);
                a[mt][2] = pack2(v2.x, v2.y);
                a[mt][3] = pack2(v3.x, v3.y);
            }
            uint32_t b[4][2];
#pragma unroll
            for (int nt = 0; nt < 4; ++nt) {
                const uint2 bv = *reinterpret_cast<const uint2*>(
                    Bs + cl * 2048 + (warpN * 32 + nt * 8 + g) * 32 + t * 8);
                b[nt][0] = bv.x;
                b[nt][1] = bv.y;
            }
#pragma unroll
            for (int mt = 0; mt < 2; ++mt)
#pragma unroll
                for (int nt = 0; nt < 4; ++nt)
                    mma16816(acc[mt][nt], a[mt], b[nt]);
        }
        bufc = (bufc + 1 >= PIPE) ? 0 : bufc + 1;
    }
    __syncthreads();   // all MMA reads done before Ls aliases the buffers

    // ---- spill logits (C-frag -> row-major [128][64], stride 65) ----
#pragma unroll
    for (int mt = 0; mt < 2; ++mt) {
        const int r0 = warpM * 32 + mt * 16 + g;
#pragma unroll
        for (int nt = 0; nt < 4; ++nt) {
            const int c0 = warpN * 32 + nt * 8 + 2 * t;
            Ls[r0 * LS_STRIDE + c0]           = acc[mt][nt][0];
            Ls[r0 * LS_STRIDE + c0 + 1]       = acc[mt][nt][1];
            Ls[(r0 + 8) * LS_STRIDE + c0]     = acc[mt][nt][2];
            Ls[(r0 + 8) * LS_STRIDE + c0 + 1] = acc[mt][nt][3];
        }
    }
    __syncthreads();

    // ---- per-row logsumexp: 2 threads per row, shfl-combined ----
    float val = 0.f;
    {
        const int row = tid >> 1;
        const int kh  = (tid & 1) * 32;
        float m = -INFINITY;
        float x[32];
#pragma unroll
        for (int k = 0; k < 32; ++k) {
            x[k] = Ls[row * LS_STRIDE + kh + k] + s_prior[kh + k];
            m = fmaxf(m, x[k]);
        }
        const float mo = __shfl_xor_sync(0xffffffffu, m, 1);
        const float mm = fmaxf(m, mo);
        float ssum = 0.f;
#pragma unroll
        for (int k = 0; k < 32; ++k)
            ssum += __expf(x[k] - mm);
        const float so = __shfl_xor_sync(0xffffffffu, ssum, 1);
        if ((tid & 1) == 0 && (rowBase + row) < nRows)
            val = mm + __logf(ssum + so);
    }
#pragma unroll
    for (int d = 16; d; d >>= 1) val += __shfl_xor_sync(0xffffffffu, val, d);
    if (lane == 0) s_red[warp] = val;
    __syncthreads();
    if (warp == 0) {
        float v = (lane < 8) ? s_red[lane] : 0.f;
#pragma unroll
        for (int d = 4; d; d >>= 1) v += __shfl_xor_sync(0xffffffffu, v, d);
        if (lane == 0) g_partials[blockIdx.x] = v;
    }
}

__global__ void final_reduce(float* __restrict__ out, int nTiles) {
    __shared__ double sred[256];
    double s = 0.0;
    for (int i = threadIdx.x; i < nTiles; i += 256) s += (double)g_partials[i];
    sred[threadIdx.x] = s;
    __syncthreads();
#pragma unroll
    for (int off = 128; off > 0; off >>= 1) {
        if (threadIdx.x < off) sred[threadIdx.x] += sred[threadIdx.x + off];
        __syncthreads();
    }
    if (threadIdx.x == 0) out[0] = (float)sred[0];
}

extern "C" void kernel_launch(void* const* d_in, const int* in_sizes, int n_in,
                              void* d_out, int out_size) {
    const float* counts = (const float*)d_in[0];   // (N, 1024) fp32
    const float* otu    = (const float*)d_in[1];   // (64, 1024) fp32
    const float* comm   = (const float*)d_in[2];   // (64,) fp32
    float* out = (float*)d_out;

    const int nRows  = in_sizes[0] / O_DIM;
    const int nTiles = (nRows + M_TILE - 1) / M_TILE;

    static bool smem_set = false;  // idempotent attribute, safe under capture
    if (!smem_set) {
        cudaFuncSetAttribute(gemm_lse, cudaFuncAttributeMaxDynamicSharedMemorySize,
                             SMEM_BYTES);
        smem_set = true;
    }

    prep_logw<<<(K_COMM * 512 + 255) / 256, 256>>>(otu);
    gemm_lse<<<nTiles, 256, SMEM_BYTES>>>(counts, comm, nRows);
    final_reduce<<<1, 256>>>(out, nTiles);
}